// round 12
// baseline (speedup 1.0000x reference)
#include <cuda_runtime.h>

static constexpr int BATCH = 8;
static constexpr int SEQ   = 16384;
static constexpr int CH    = 256;
static constexpr int TOPN  = 2048;
static constexpr int ROWS  = BATCH * SEQ;     // 131072
static constexpr int QUADS = ROWS / 4;        // 32768

static constexpr int K1_GRID    = 444;        // 148 SMs * 3 resident CTAs
static constexpr int K1_THREADS = 256;        // 8 warps
static constexpr int K1_WARPS_TOTAL = K1_GRID * (K1_THREADS / 32);  // 3552

static constexpr int SLICES     = 32;         // gather CTAs per batch
static constexpr int SLICE_ROWS = TOPN / SLICES;  // 64 rows per CTA
static constexpr int G_THREADS  = 512;        // 16 warps

__device__ float g_score[ROWS];
__device__ float g_psum[K1_GRID];
__device__ float g_psq[K1_GRID];

// ---------------------------------------------------------------------------
// K1: persistent grid-stride. A warp covers 4 rows, 8 lanes per row
// (lane = 8*subrow + pos). 8 front-batched float4 streaming loads per thread;
// row reduce = 3-step shfl butterfly (4 rows simultaneously in one register).
// ---------------------------------------------------------------------------
__global__ __launch_bounds__(K1_THREADS, 3) void score_kernel(const float* __restrict__ x,
                                                              const float* __restrict__ w,
                                                              const float* __restrict__ bias) {
    const int warp   = threadIdx.x >> 5;
    const int lane   = threadIdx.x & 31;
    const int subrow = lane >> 3;
    const int pos    = lane & 7;
    const int gw     = blockIdx.x * (K1_THREADS / 32) + warp;

    const float4* wv = (const float4*)w;
    float4 W[8];
#pragma unroll
    for (int j = 0; j < 8; j++) W[j] = wv[pos + 8*j];
    const float bb = bias[0];

    float S = 0.f, Q = 0.f;

    for (int quad = gw; quad < QUADS; quad += K1_WARPS_TOTAL) {
        const size_t row = (size_t)quad * 4 + subrow;
        const float4* xb = (const float4*)(x + row * CH);

        float4 v[8];
#pragma unroll
        for (int j = 0; j < 8; j++) v[j] = __ldcs(xb + pos + 8*j);

        float d = 0.f;
#pragma unroll
        for (int j = 0; j < 8; j++)
            d += v[j].x*W[j].x + v[j].y*W[j].y + v[j].z*W[j].z + v[j].w*W[j].w;

        d += __shfl_xor_sync(0xffffffffu, d, 4);
        d += __shfl_xor_sync(0xffffffffu, d, 2);
        d += __shfl_xor_sync(0xffffffffu, d, 1);

        if (pos == 0) {
            float c = d + bb;
            __stcs(&g_score[row], c);
            S += c;
            Q += c * c;
        }
    }

#pragma unroll
    for (int off = 16; off > 0; off >>= 1) {
        S += __shfl_xor_sync(0xffffffffu, S, off);
        Q += __shfl_xor_sync(0xffffffffu, Q, off);
    }
    __shared__ float ws[K1_THREADS / 32], wq[K1_THREADS / 32];
    if (lane == 0) { ws[warp] = S; wq[warp] = Q; }
    __syncthreads();
    if (threadIdx.x < 32) {
        float s = (threadIdx.x < K1_THREADS / 32) ? ws[threadIdx.x] : 0.f;
        float q = (threadIdx.x < K1_THREADS / 32) ? wq[threadIdx.x] : 0.f;
#pragma unroll
        for (int off = 4; off > 0; off >>= 1) {
            s += __shfl_xor_sync(0xffffffffu, s, off);
            q += __shfl_xor_sync(0xffffffffu, q, off);
        }
        if (threadIdx.x == 0) { g_psum[blockIdx.x] = s; g_psq[blockIdx.x] = q; }
    }
}

// ---------------------------------------------------------------------------
// K2 (fused select + gather): 256 CTAs = 8 batches x 32 slices.
// Each CTA independently recomputes mean/var and the stable compaction scan
// of its batch (scores are L2-hot; redundancy instead of synchronization),
// keeps the 64 output rows whose ranks fall in its slice, and gathers them.
// Fast path: ReLU zeros (normalized <= 0) lead a stable ascending argsort in
// index order -> rank = prefix count. Slow path (T < TOPN, practically
// unreachable): 2048 rounds of "min key greater than last", recomputed on
// the fly -- zero scratch, zero cross-CTA communication.
// ---------------------------------------------------------------------------
__global__ __launch_bounds__(G_THREADS) void select_gather_kernel(
        const float* __restrict__ xs,
        const float* __restrict__ gamma,
        const float* __restrict__ beta,
        float* __restrict__ out) {
    const int tid   = threadIdx.x;
    const int lane  = tid & 31;
    const int warp  = tid >> 5;
    const int b     = blockIdx.x >> 5;          // batch
    const int slice = blockIdx.x & (SLICES-1);  // 0..31
    const unsigned lo = (unsigned)(slice * SLICE_ROWS);
    const unsigned hi = lo + SLICE_ROWS;

    __shared__ float red1[G_THREADS], red2[G_THREADS];
    __shared__ unsigned warpsum[16], warpexcl[16];
    __shared__ unsigned total_s;
    __shared__ unsigned sidx[SLICE_ROWS];

    // --- mean / var from K1 partials ---
    {
        float S = (tid < K1_GRID) ? g_psum[tid] : 0.f;
        float Q = (tid < K1_GRID) ? g_psq[tid]  : 0.f;
        red1[tid] = S; red2[tid] = Q;
    }
    __syncthreads();
    for (int off = 256; off > 0; off >>= 1) {
        if (tid < off) { red1[tid] += red1[tid + off]; red2[tid] += red2[tid + off]; }
        __syncthreads();
    }
    const float mean = red1[0] / (float)ROWS;
    float var  = red2[0] / (float)ROWS - mean * mean;
    if (var < 0.f) var = 0.f;
    const float scale = rsqrtf(var + 1e-5f) * gamma[0];
    const float shift = beta[0] - mean * scale;

    // --- compaction scan: 32 elements per thread ---
    const float* sc = g_score + (size_t)b * SEQ;
    const int base = tid * 32;
    const float4* p4 = (const float4*)(sc + base);
    unsigned m0 = 0;
#pragma unroll
    for (int j = 0; j < 8; j++) {
        float4 v = p4[j];
        if (fmaf(v.x, scale, shift) <= 0.f) m0 |= 1u << (4*j + 0);
        if (fmaf(v.y, scale, shift) <= 0.f) m0 |= 1u << (4*j + 1);
        if (fmaf(v.z, scale, shift) <= 0.f) m0 |= 1u << (4*j + 2);
        if (fmaf(v.w, scale, shift) <= 0.f) m0 |= 1u << (4*j + 3);
    }
    const unsigned c = (unsigned)__popc(m0);

    // block exclusive scan (16 warps)
    unsigned incl = c;
#pragma unroll
    for (int off = 1; off < 32; off <<= 1) {
        unsigned n = __shfl_up_sync(0xffffffffu, incl, off);
        if (lane >= off) incl += n;
    }
    if (lane == 31) warpsum[warp] = incl;
    __syncthreads();
    if (tid < 16) {
        unsigned wv = warpsum[tid];
        unsigned wincl = wv;
#pragma unroll
        for (int off = 1; off < 16; off <<= 1) {
            unsigned n = __shfl_up_sync(0x0000ffffu, wincl, off);
            if (tid >= off) wincl += n;
        }
        warpexcl[tid] = wincl - wv;
        if (tid == 15) total_s = wincl;
    }
    __syncthreads();
    const unsigned T = total_s;

    if (T >= (unsigned)TOPN) {
        // fast path: record indices whose rank falls in [lo, hi)
        unsigned r = warpexcl[warp] + (incl - c);
        if (r < hi && r + c > lo) {
#pragma unroll
            for (int j = 0; j < 32; j++) {
                if (m0 & (1u << j)) {
                    if (r >= lo && r < hi) sidx[r - lo] = (unsigned)(base + j);
                    r++;
                }
            }
        }
    } else {
        // ===== slow path: TOPN rounds of min-key-greater-than-last =====
        __shared__ unsigned long long mv[G_THREADS];
        unsigned long long last = 0ULL;
        for (int r = 0; r < TOPN; r++) {
            unsigned long long best = ~0ULL;
#pragma unroll
            for (int j = 0; j < 32; j++) {
                int i = base + j;
                float rv = fmaxf(0.f, fmaf(sc[i], scale, shift));
                unsigned long long k =
                    ((unsigned long long)__float_as_uint(rv) << 14) | (unsigned)i;
                if ((r == 0 || k > last) && k < best) best = k;
            }
            mv[tid] = best;
            __syncthreads();
            for (int off = 256; off > 0; off >>= 1) {
                if (tid < off && mv[tid + off] < mv[tid]) mv[tid] = mv[tid + off];
                __syncthreads();
            }
            last = mv[0];
            if (tid == 0 && (unsigned)r >= lo && (unsigned)r < hi)
                sidx[r - lo] = (unsigned)(last & 0x3fffu);
            __syncthreads();
        }
    }
    __syncthreads();

    // --- gather 64 rows: 8 threads per row, 8 front-batched float4 each ---
    const int lrow = tid >> 3;                   // 0..63
    const int pos  = tid & 7;                    // 0..7
    const unsigned idx = sidx[lrow];
    const float4* src = (const float4*)(xs + ((size_t)b * SEQ + idx) * CH);
    float4* dst = (float4*)(out + ((size_t)b * TOPN + lo + lrow) * CH);

    float4 v[8];
#pragma unroll
    for (int j = 0; j < 8; j++) v[j] = __ldcs(src + pos + 8*j);
#pragma unroll
    for (int j = 0; j < 8; j++) __stcs(dst + pos + 8*j, v[j]);
}

// ---------------------------------------------------------------------------
extern "C" void kernel_launch(void* const* d_in, const int* in_sizes, int n_in,
                              void* d_out, int out_size) {
    const float* x_in  = (const float*)d_in[0];
    const float* x_sel = (const float*)d_in[1];
    const float* w     = (const float*)d_in[2];
    const float* bias  = (const float*)d_in[3];
    const float* gamma = (const float*)d_in[4];
    const float* beta  = (const float*)d_in[5];
    float* out = (float*)d_out;

    score_kernel<<<K1_GRID, K1_THREADS>>>(x_in, w, bias);
    select_gather_kernel<<<BATCH * SLICES, G_THREADS>>>(x_sel, gamma, beta, out);
}